// round 12
// baseline (speedup 1.0000x reference)
#include <cuda_runtime.h>
#include <cuda_bf16.h>
#include <cstdint>

#define IN_F   4096
#define OUT_F  768
#define BITS   6144
#define BATCH  1024

#define BM 64
#define BN 64
#define BKK 64
#define KSPLIT 4
#define KSLICE (IN_F / KSPLIT)   // 1024
#define NKC (KSLICE / BKK)       // 16
#define NSTAGE 4
#define GX (OUT_F / BN)          // 12
#define GY (BATCH / BM)          // 16
#define A_ST (BM * BKK)          // 4096 u16
#define B_ST (BN * BKK)          // 4096 u16
#define DSMEM_BYTES (NSTAGE * (A_ST + B_ST) * 2)   // 65536
#define NLOSS 768                // loss blocks

// ---------------- device scratch ----------------
__device__ __nv_bfloat16 g_wT[(size_t)OUT_F * IN_F];
__device__ __nv_bfloat16 g_lat[(size_t)BATCH * IN_F];
__device__ float g_pred[KSPLIT][(size_t)BATCH * OUT_F];   // split-K partials (fp32)
__device__ float g_reg_part[3072];
__device__ float g_recon_part[NLOSS];
__device__ int   g_ticket;

// ---------------- helpers ----------------
__device__ __forceinline__ float tanh_fast(float x) {
    float y; asm("tanh.approx.f32 %0, %1;" : "=f"(y) : "f"(x)); return y;
}
__device__ __forceinline__ uint32_t cvta_s(const void* p) {
    return (uint32_t)__cvta_generic_to_shared(p);
}
#define CP_ASYNC16(s, g) asm volatile("cp.async.cg.shared.global [%0], [%1], 16;\n" :: "r"(s), "l"(g))
#define CP_COMMIT        asm volatile("cp.async.commit_group;\n" ::: "memory")
#define CP_WAIT0         asm volatile("cp.async.wait_group 0;\n" ::: "memory")
#define CP_WAIT1         asm volatile("cp.async.wait_group 1;\n" ::: "memory")
#define CP_WAIT2         asm volatile("cp.async.wait_group 2;\n" ::: "memory")
#define LDSM4(r0, r1, r2, r3, a) \
    asm volatile("ldmatrix.sync.aligned.m8n8.x4.shared.b16 {%0,%1,%2,%3}, [%4];\n" \
                 : "=r"(r0), "=r"(r1), "=r"(r2), "=r"(r3) : "r"(a))
#define MMA(d, a, b0, b1) \
    asm volatile("mma.sync.aligned.m16n8k16.row.col.f32.bf16.bf16.f32 " \
                 "{%0,%1,%2,%3},{%4,%5,%6,%7},{%8,%9},{%0,%1,%2,%3};\n" \
                 : "+f"(d[0]), "+f"(d[1]), "+f"(d[2]), "+f"(d[3]) \
                 : "r"(a[0]), "r"(a[1]), "r"(a[2]), "r"(a[3]), "r"(b0), "r"(b1))

// ---------------- fused pre-pass (unchanged, validated) ----------------
__global__ void k_pre(const float* __restrict__ w, const float* __restrict__ lat) {
    int bx = blockIdx.x;
    int t = threadIdx.x;

    if (bx < 3072) {
        __shared__ float s_iw[32][33];
        __shared__ float s_red[8];
        const float pwh[8] = {0.5f, 1.f, 2.f, 4.f, 8.f, 16.f, 32.f, -64.f};

        int k0 = (bx & 127) * 32;
        int n0 = (bx >> 7) * 32;

        float regloc = 0.f;
#pragma unroll
        for (int i = 0; i < 4; i++) {
            int c = t + i * 256;
            int kk = c >> 5, nn = c & 31;
            const float4* p = reinterpret_cast<const float4*>(
                w + (size_t)(k0 + kk) * BITS + (size_t)(n0 + nn) * 8);
            float4 w0 = p[0], w1 = p[1];
            float xs[8] = {w0.x, w0.y, w0.z, w0.w, w1.x, w1.y, w1.z, w1.w};
            float iwt = 0.f, sab = 0.f;
#pragma unroll
            for (int b = 0; b < 8; b++) {
                float th = tanh_fast(0.5f * xs[b]);
                iwt = fmaf(th, pwh[b], iwt);
                sab += fabsf(th);
            }
            s_iw[kk][nn] = iwt - 0.5f;
            regloc += fmaf(-0.5f, sab, 4.0f);
        }
        __syncthreads();
#pragma unroll
        for (int i = 0; i < 4; i++) {
            int c = t + i * 256;
            int nn = c >> 5, kk = c & 31;
            g_wT[(size_t)(n0 + nn) * IN_F + (k0 + kk)] = __float2bfloat16(s_iw[kk][nn]);
        }
#pragma unroll
        for (int o = 16; o > 0; o >>= 1)
            regloc += __shfl_xor_sync(0xffffffffu, regloc, o);
        if ((t & 31) == 0) s_red[t >> 5] = regloc;
        __syncthreads();
        if (t == 0) {
            float s = 0.f;
#pragma unroll
            for (int i = 0; i < 8; i++) s += s_red[i];
            g_reg_part[bx] = s;
        }
    } else {
        int i = (bx - 3072) * 256 + t;
        const int stride = 1024 * 256;
        const float4* src = reinterpret_cast<const float4*>(lat);
        __nv_bfloat162* o = reinterpret_cast<__nv_bfloat162*>(g_lat);
        float4 v[4];
#pragma unroll
        for (int j = 0; j < 4; j++) v[j] = src[i + j * stride];
#pragma unroll
        for (int j = 0; j < 4; j++) {
            int idx = i + j * stride;
            o[2 * idx]     = __floats2bfloat162_rn(v[j].x, v[j].y);
            o[2 * idx + 1] = __floats2bfloat162_rn(v[j].z, v[j].w);
        }
    }
}

// int_sum(r,n)/255 from true_sum
__device__ __forceinline__ float tval(const float* __restrict__ ts, int r, int n) {
    const float4* p = reinterpret_cast<const float4*>(ts + ((size_t)r * OUT_F + n) * 8);
    float4 a = p[0], b = p[1];
    return (a.x + 2.f * a.y + 4.f * a.z + 8.f * a.w
            + 16.f * b.x + 32.f * b.y + 64.f * b.z - 128.f * b.w) * (1.0f / 255.0f);
}

// stage loader: A 2x16B + B 2x16B per thread (swizzled, BKK=64)
__device__ __forceinline__ void load_tile(
    uint16_t* Asb, uint16_t* Bsb,
    const __nv_bfloat16* gA, const __nv_bfloat16* gB, int kbase, int t)
{
#pragma unroll
    for (int j = 0; j < 2; j++) {
        int id = t + j * 256;
        int row = id >> 3, c = id & 7;
        int sw = (c ^ (row & 7)) << 3;
        CP_ASYNC16(cvta_s(&Asb[row * BKK + sw]),
                   gA + (size_t)row * IN_F + kbase + c * 8);
        CP_ASYNC16(cvta_s(&Bsb[row * BKK + sw]),
                   gB + (size_t)row * IN_F + kbase + c * 8);
    }
}

// split-K GEMM: 64x64 tile, K-slice 1024, 4-stage cp.async (R6/R11-validated body).
// grid (12,16,4) = 768 CTAs, 3 CTAs/SM resident.
__global__ void __launch_bounds__(256, 3)
k_gemm() {
    extern __shared__ __align__(16) uint8_t dsm[];
    uint16_t* As = (uint16_t*)dsm;             // NSTAGE * A_ST
    uint16_t* Bs = As + NSTAGE * A_ST;         // NSTAGE * B_ST

    int n0 = blockIdx.x * BN;
    int m0 = blockIdx.y * BM;
    int z  = blockIdx.z;
    int t = threadIdx.x;
    int wid = t >> 5, lane = t & 31;
    int wm = wid & 3, wn = wid >> 2;           // 4 M-stripes x 2 N-stripes (16x32)

    const __nv_bfloat16* gA = g_lat + (size_t)m0 * IN_F + z * KSLICE;
    const __nv_bfloat16* gB = g_wT + (size_t)n0 * IN_F + z * KSLICE;

    float acc[4][4] = {};

    int rA = wm * 16 + (lane & 15);
    int kA = lane >> 4;
    int rBq = ((lane >> 4) << 3) + (lane & 7);
    int kB = (lane >> 3) & 1;

    // prologue: stages 0..2
    load_tile(As, Bs, gA, gB, 0, t); CP_COMMIT;
    load_tile(As + A_ST, Bs + B_ST, gA, gB, BKK, t); CP_COMMIT;
    load_tile(As + 2 * A_ST, Bs + 2 * B_ST, gA, gB, 2 * BKK, t); CP_COMMIT;

    int buf = 0;
    for (int kc = 0; kc < NKC; kc++) {
        if (kc < NKC - 2)       { CP_WAIT2; }
        else if (kc == NKC - 2) { CP_WAIT1; }
        else                    { CP_WAIT0; }
        __syncthreads();

        if (kc + 3 < NKC) {
            int b3 = buf + 3; if (b3 >= NSTAGE) b3 -= NSTAGE;
            load_tile(As + b3 * A_ST, Bs + b3 * B_ST, gA, gB, (kc + 3) * BKK, t);
            CP_COMMIT;
        }

        const uint16_t* Ab = As + buf * A_ST;
        const uint16_t* Bb = Bs + buf * B_ST;
#pragma unroll
        for (int s = 0; s < 4; s++) {
            int cb = s * 2;
            uint32_t af[4], bf[2][4];
            {
                int c = cb + kA;
                LDSM4(af[0], af[1], af[2], af[3],
                      cvta_s(&Ab[rA * BKK + ((c ^ (rA & 7)) << 3)]));
            }
#pragma unroll
            for (int j = 0; j < 2; j++) {
                int r = wn * 32 + j * 16 + rBq;
                int c = cb + kB;
                LDSM4(bf[j][0], bf[j][1], bf[j][2], bf[j][3],
                      cvta_s(&Bb[r * BKK + ((c ^ (r & 7)) << 3)]));
            }
#pragma unroll
            for (int j = 0; j < 2; j++) {
                MMA(acc[2 * j],     af, bf[j][0], bf[j][1]);
                MMA(acc[2 * j + 1], af, bf[j][2], bf[j][3]);
            }
        }
        buf++; if (buf >= NSTAGE) buf = 0;
    }

    // store raw fp32 partials (deterministic: per-z buffer)
    float* P = g_pred[z];
    int gid = lane >> 2, tig = lane & 3;
#pragma unroll
    for (int j = 0; j < 4; j++) {
        int r  = m0 + wm * 16 + gid;
        int nc = n0 + wn * 32 + (j >> 1) * 16 + (j & 1) * 8 + tig * 2;
        *reinterpret_cast<float2*>(&P[(size_t)r * OUT_F + nc]) =
            make_float2(acc[j][0], acc[j][1]);
        *reinterpret_cast<float2*>(&P[(size_t)(r + 8) * OUT_F + nc]) =
            make_float2(acc[j][2], acc[j][3]);
    }
}

// loss: pred = sum_z p_z, (pred/255 - int_sum/255)^2; last-block final reduction
__global__ void k_loss(const float* __restrict__ ts,
                       float* __restrict__ out, int out_size) {
    __shared__ float s_red[8], s_red2[8];
    __shared__ int s_last;
    int t = threadIdx.x, bid = blockIdx.x;
    int base = (bid * 256 + t) * 4;
    int r = base / OUT_F, n = base % OUT_F;

    float4 p = *reinterpret_cast<const float4*>(&g_pred[0][base]);
#pragma unroll
    for (int z = 1; z < KSPLIT; z++) {
        float4 q = *reinterpret_cast<const float4*>(&g_pred[z][base]);
        p.x += q.x; p.y += q.y; p.z += q.z; p.w += q.w;
    }
    float e0 = fmaf(p.x, 1.f / 255.f, -tval(ts, r, n));
    float e1 = fmaf(p.y, 1.f / 255.f, -tval(ts, r, n + 1));
    float e2 = fmaf(p.z, 1.f / 255.f, -tval(ts, r, n + 2));
    float e3 = fmaf(p.w, 1.f / 255.f, -tval(ts, r, n + 3));
    float lsum = e0 * e0 + e1 * e1 + e2 * e2 + e3 * e3;

#pragma unroll
    for (int o = 16; o > 0; o >>= 1)
        lsum += __shfl_xor_sync(0xffffffffu, lsum, o);
    if ((t & 31) == 0) s_red[t >> 5] = lsum;
    __syncthreads();

    if (t == 0) {
        float s = 0.f;
#pragma unroll
        for (int i = 0; i < 8; i++) s += s_red[i];
        g_recon_part[bid] = s;
        __threadfence();
        int old = atomicAdd(&g_ticket, 1);
        s_last = (old == NLOSS - 1) ? 1 : 0;
    }
    __syncthreads();

    if (s_last) {
        float rr = 0.f, ss = 0.f;
        for (int i = t; i < 3072; i += 256) rr += __ldcg(&g_reg_part[i]);
        for (int i = t; i < NLOSS; i += 256) ss += __ldcg(&g_recon_part[i]);
#pragma unroll
        for (int o = 16; o > 0; o >>= 1) {
            rr += __shfl_xor_sync(0xffffffffu, rr, o);
            ss += __shfl_xor_sync(0xffffffffu, ss, o);
        }
        if ((t & 31) == 0) { s_red[t >> 5] = rr; s_red2[t >> 5] = ss; }
        __syncthreads();
        if (t == 0) {
            float R = 0.f, S = 0.f;
#pragma unroll
            for (int i = 0; i < 8; i++) { R += s_red[i]; S += s_red2[i]; }
            float recon = S * (1.0f / ((float)BATCH * OUT_F));
            float reg   = 0.001f * R * (1.0f / ((float)IN_F * (float)BITS));
            if (out_size > 0) out[0] = recon + reg;
            if (out_size > 1) out[1] = recon;
            if (out_size > 2) out[2] = reg;
            g_ticket = 0;   // reset for next graph replay
        }
    }
}

// ---------------- launch ----------------
extern "C" void kernel_launch(void* const* d_in, const int* in_sizes, int n_in,
                              void* d_out, int out_size) {
    const float* latent   = (const float*)d_in[0];
    const float* true_sum = (const float*)d_in[1];
    const float* weight   = (const float*)d_in[2];

    static int smem_set = 0;
    if (!smem_set) {
        cudaFuncSetAttribute(k_gemm, cudaFuncAttributeMaxDynamicSharedMemorySize,
                             DSMEM_BYTES);
        smem_set = 1;
    }

    k_pre<<<4096, 256>>>(weight, latent);
    k_gemm<<<dim3(GX, GY, KSPLIT), 256, DSMEM_BYTES>>>();
    k_loss<<<NLOSS, 256>>>(true_sum, (float*)d_out, out_size);
}

// round 13
// speedup vs baseline: 1.0206x; 1.0206x over previous
#include <cuda_runtime.h>
#include <cuda_bf16.h>
#include <cstdint>

#define IN_F   4096
#define OUT_F  768
#define BITS   6144
#define BATCH  1024

#define BM 64
#define BN 64
#define BKK 64
#define KSPLIT 2
#define KSLICE (IN_F / KSPLIT)   // 2048
#define NKC (KSLICE / BKK)       // 32
#define NSTAGE 4
#define GX (OUT_F / BN)          // 12
#define GY (BATCH / BM)          // 16
#define A_ST (BM * BKK)          // 4096 u16
#define B_ST (BN * BKK)          // 4096 u16
#define DSMEM_BYTES (NSTAGE * (A_ST + B_ST) * 2)   // 65536
#define NLOSS 768                // loss blocks

// ---------------- device scratch ----------------
__device__ __nv_bfloat16 g_wT[(size_t)OUT_F * IN_F];
__device__ __nv_bfloat16 g_lat[(size_t)BATCH * IN_F];
__device__ float g_pred[KSPLIT][(size_t)BATCH * OUT_F];   // split-K partials (fp32)
__device__ float g_reg_part[3072];
__device__ float g_recon_part[NLOSS];
__device__ int   g_ticket;

// ---------------- helpers ----------------
__device__ __forceinline__ float tanh_fast(float x) {
    float y; asm("tanh.approx.f32 %0, %1;" : "=f"(y) : "f"(x)); return y;
}
__device__ __forceinline__ uint32_t cvta_s(const void* p) {
    return (uint32_t)__cvta_generic_to_shared(p);
}
#define CP_ASYNC16(s, g) asm volatile("cp.async.cg.shared.global [%0], [%1], 16;\n" :: "r"(s), "l"(g))
#define CP_COMMIT        asm volatile("cp.async.commit_group;\n" ::: "memory")
#define CP_WAIT0         asm volatile("cp.async.wait_group 0;\n" ::: "memory")
#define CP_WAIT1         asm volatile("cp.async.wait_group 1;\n" ::: "memory")
#define CP_WAIT2         asm volatile("cp.async.wait_group 2;\n" ::: "memory")
#define LDSM4(r0, r1, r2, r3, a) \
    asm volatile("ldmatrix.sync.aligned.m8n8.x4.shared.b16 {%0,%1,%2,%3}, [%4];\n" \
                 : "=r"(r0), "=r"(r1), "=r"(r2), "=r"(r3) : "r"(a))
#define MMA(d, a, b0, b1) \
    asm volatile("mma.sync.aligned.m16n8k16.row.col.f32.bf16.bf16.f32 " \
                 "{%0,%1,%2,%3},{%4,%5,%6,%7},{%8,%9},{%0,%1,%2,%3};\n" \
                 : "+f"(d[0]), "+f"(d[1]), "+f"(d[2]), "+f"(d[3]) \
                 : "r"(a[0]), "r"(a[1]), "r"(a[2]), "r"(a[3]), "r"(b0), "r"(b1))

// ---------------- fused pre-pass ----------------
// blocks [0,3072): sigmoid(weight) -> reg partials + int_weights^T bf16
//   R13 change: all 8 LDG.128 hoisted ahead of compute (MLP=8)
// blocks [3072,4096): latent fp32 -> bf16
__global__ void k_pre(const float* __restrict__ w, const float* __restrict__ lat) {
    int bx = blockIdx.x;
    int t = threadIdx.x;

    if (bx < 3072) {
        __shared__ float s_iw[32][33];
        __shared__ float s_red[8];
        const float pwh[8] = {0.5f, 1.f, 2.f, 4.f, 8.f, 16.f, 32.f, -64.f};

        int k0 = (bx & 127) * 32;
        int n0 = (bx >> 7) * 32;

        // hoisted loads: 8 x LDG.128 in flight before any compute
        float4 d[8];
#pragma unroll
        for (int i = 0; i < 4; i++) {
            int c = t + i * 256;
            int kk = c >> 5, nn = c & 31;
            const float4* p = reinterpret_cast<const float4*>(
                w + (size_t)(k0 + kk) * BITS + (size_t)(n0 + nn) * 8);
            d[2 * i]     = p[0];
            d[2 * i + 1] = p[1];
        }

        float regloc = 0.f;
#pragma unroll
        for (int i = 0; i < 4; i++) {
            int c = t + i * 256;
            int kk = c >> 5, nn = c & 31;
            float xs[8] = {d[2*i].x, d[2*i].y, d[2*i].z, d[2*i].w,
                           d[2*i+1].x, d[2*i+1].y, d[2*i+1].z, d[2*i+1].w};
            float iwt = 0.f, sab = 0.f;
#pragma unroll
            for (int b = 0; b < 8; b++) {
                float th = tanh_fast(0.5f * xs[b]);
                iwt = fmaf(th, pwh[b], iwt);
                sab += fabsf(th);
            }
            s_iw[kk][nn] = iwt - 0.5f;
            regloc += fmaf(-0.5f, sab, 4.0f);
        }
        __syncthreads();
#pragma unroll
        for (int i = 0; i < 4; i++) {
            int c = t + i * 256;
            int nn = c >> 5, kk = c & 31;
            g_wT[(size_t)(n0 + nn) * IN_F + (k0 + kk)] = __float2bfloat16(s_iw[kk][nn]);
        }
#pragma unroll
        for (int o = 16; o > 0; o >>= 1)
            regloc += __shfl_xor_sync(0xffffffffu, regloc, o);
        if ((t & 31) == 0) s_red[t >> 5] = regloc;
        __syncthreads();
        if (t == 0) {
            float s = 0.f;
#pragma unroll
            for (int i = 0; i < 8; i++) s += s_red[i];
            g_reg_part[bx] = s;
        }
    } else {
        int i = (bx - 3072) * 256 + t;
        const int stride = 1024 * 256;
        const float4* src = reinterpret_cast<const float4*>(lat);
        __nv_bfloat162* o = reinterpret_cast<__nv_bfloat162*>(g_lat);
        float4 v[4];
#pragma unroll
        for (int j = 0; j < 4; j++) v[j] = src[i + j * stride];
#pragma unroll
        for (int j = 0; j < 4; j++) {
            int idx = i + j * stride;
            o[2 * idx]     = __floats2bfloat162_rn(v[j].x, v[j].y);
            o[2 * idx + 1] = __floats2bfloat162_rn(v[j].z, v[j].w);
        }
    }
}

// int_sum(r,n)/255 from true_sum
__device__ __forceinline__ float tval(const float* __restrict__ ts, int r, int n) {
    const float4* p = reinterpret_cast<const float4*>(ts + ((size_t)r * OUT_F + n) * 8);
    float4 a = p[0], b = p[1];
    return (a.x + 2.f * a.y + 4.f * a.z + 8.f * a.w
            + 16.f * b.x + 32.f * b.y + 64.f * b.z - 128.f * b.w) * (1.0f / 255.0f);
}

// stage loader: A 2x16B + B 2x16B per thread (swizzled, BKK=64)
__device__ __forceinline__ void load_tile(
    uint16_t* Asb, uint16_t* Bsb,
    const __nv_bfloat16* gA, const __nv_bfloat16* gB, int kbase, int t)
{
#pragma unroll
    for (int j = 0; j < 2; j++) {
        int id = t + j * 256;
        int row = id >> 3, c = id & 7;
        int sw = (c ^ (row & 7)) << 3;
        CP_ASYNC16(cvta_s(&Asb[row * BKK + sw]),
                   gA + (size_t)row * IN_F + kbase + c * 8);
        CP_ASYNC16(cvta_s(&Bsb[row * BKK + sw]),
                   gB + (size_t)row * IN_F + kbase + c * 8);
    }
}

// split-K GEMM (R11-verbatim, measured best): 64x64 tile, K-slice 2048,
// 4-stage cp.async, grid (12,16,2) = 384 CTAs, 3 CTAs/SM -> single resident wave.
__global__ void __launch_bounds__(256, 3)
k_gemm() {
    extern __shared__ __align__(16) uint8_t dsm[];
    uint16_t* As = (uint16_t*)dsm;             // NSTAGE * A_ST
    uint16_t* Bs = As + NSTAGE * A_ST;         // NSTAGE * B_ST

    int n0 = blockIdx.x * BN;
    int m0 = blockIdx.y * BM;
    int z  = blockIdx.z;
    int t = threadIdx.x;
    int wid = t >> 5, lane = t & 31;
    int wm = wid & 3, wn = wid >> 2;           // 4 M-stripes x 2 N-stripes (16x32)

    const __nv_bfloat16* gA = g_lat + (size_t)m0 * IN_F + z * KSLICE;
    const __nv_bfloat16* gB = g_wT + (size_t)n0 * IN_F + z * KSLICE;

    float acc[4][4] = {};

    int rA = wm * 16 + (lane & 15);
    int kA = lane >> 4;
    int rBq = ((lane >> 4) << 3) + (lane & 7);
    int kB = (lane >> 3) & 1;

    // prologue: stages 0..2
    load_tile(As, Bs, gA, gB, 0, t); CP_COMMIT;
    load_tile(As + A_ST, Bs + B_ST, gA, gB, BKK, t); CP_COMMIT;
    load_tile(As + 2 * A_ST, Bs + 2 * B_ST, gA, gB, 2 * BKK, t); CP_COMMIT;

    int buf = 0;
    for (int kc = 0; kc < NKC; kc++) {
        if (kc < NKC - 2)       { CP_WAIT2; }
        else if (kc == NKC - 2) { CP_WAIT1; }
        else                    { CP_WAIT0; }
        __syncthreads();

        if (kc + 3 < NKC) {
            int b3 = buf + 3; if (b3 >= NSTAGE) b3 -= NSTAGE;
            load_tile(As + b3 * A_ST, Bs + b3 * B_ST, gA, gB, (kc + 3) * BKK, t);
            CP_COMMIT;
        }

        const uint16_t* Ab = As + buf * A_ST;
        const uint16_t* Bb = Bs + buf * B_ST;
#pragma unroll
        for (int s = 0; s < 4; s++) {
            int cb = s * 2;
            uint32_t af[4], bf[2][4];
            {
                int c = cb + kA;
                LDSM4(af[0], af[1], af[2], af[3],
                      cvta_s(&Ab[rA * BKK + ((c ^ (rA & 7)) << 3)]));
            }
#pragma unroll
            for (int j = 0; j < 2; j++) {
                int r = wn * 32 + j * 16 + rBq;
                int c = cb + kB;
                LDSM4(bf[j][0], bf[j][1], bf[j][2], bf[j][3],
                      cvta_s(&Bb[r * BKK + ((c ^ (r & 7)) << 3)]));
            }
#pragma unroll
            for (int j = 0; j < 2; j++) {
                MMA(acc[2 * j],     af, bf[j][0], bf[j][1]);
                MMA(acc[2 * j + 1], af, bf[j][2], bf[j][3]);
            }
        }
        buf++; if (buf >= NSTAGE) buf = 0;
    }

    // store raw fp32 partials (deterministic: per-z buffer)
    float* P = g_pred[z];
    int gid = lane >> 2, tig = lane & 3;
#pragma unroll
    for (int j = 0; j < 4; j++) {
        int r  = m0 + wm * 16 + gid;
        int nc = n0 + wn * 32 + (j >> 1) * 16 + (j & 1) * 8 + tig * 2;
        *reinterpret_cast<float2*>(&P[(size_t)r * OUT_F + nc]) =
            make_float2(acc[j][0], acc[j][1]);
        *reinterpret_cast<float2*>(&P[(size_t)(r + 8) * OUT_F + nc]) =
            make_float2(acc[j][2], acc[j][3]);
    }
}

// loss: pred = p0+p1, (pred/255 - int_sum/255)^2; last-block final reduction
__global__ void k_loss(const float* __restrict__ ts,
                       float* __restrict__ out, int out_size) {
    __shared__ float s_red[8], s_red2[8];
    __shared__ int s_last;
    int t = threadIdx.x, bid = blockIdx.x;
    int base = (bid * 256 + t) * 4;
    int r = base / OUT_F, n = base % OUT_F;

    float4 p0 = *reinterpret_cast<const float4*>(&g_pred[0][base]);
    float4 p1 = *reinterpret_cast<const float4*>(&g_pred[1][base]);
    float e0 = fmaf(p0.x + p1.x, 1.f / 255.f, -tval(ts, r, n));
    float e1 = fmaf(p0.y + p1.y, 1.f / 255.f, -tval(ts, r, n + 1));
    float e2 = fmaf(p0.z + p1.z, 1.f / 255.f, -tval(ts, r, n + 2));
    float e3 = fmaf(p0.w + p1.w, 1.f / 255.f, -tval(ts, r, n + 3));
    float lsum = e0 * e0 + e1 * e1 + e2 * e2 + e3 * e3;

#pragma unroll
    for (int o = 16; o > 0; o >>= 1)
        lsum += __shfl_xor_sync(0xffffffffu, lsum, o);
    if ((t & 31) == 0) s_red[t >> 5] = lsum;
    __syncthreads();

    if (t == 0) {
        float s = 0.f;
#pragma unroll
        for (int i = 0; i < 8; i++) s += s_red[i];
        g_recon_part[bid] = s;
        __threadfence();
        int old = atomicAdd(&g_ticket, 1);
        s_last = (old == NLOSS - 1) ? 1 : 0;
    }
    __syncthreads();

    if (s_last) {
        float rr = 0.f, ss = 0.f;
        for (int i = t; i < 3072; i += 256) rr += __ldcg(&g_reg_part[i]);
        for (int i = t; i < NLOSS; i += 256) ss += __ldcg(&g_recon_part[i]);
#pragma unroll
        for (int o = 16; o > 0; o >>= 1) {
            rr += __shfl_xor_sync(0xffffffffu, rr, o);
            ss += __shfl_xor_sync(0xffffffffu, ss, o);
        }
        if ((t & 31) == 0) { s_red[t >> 5] = rr; s_red2[t >> 5] = ss; }
        __syncthreads();
        if (t == 0) {
            float R = 0.f, S = 0.f;
#pragma unroll
            for (int i = 0; i < 8; i++) { R += s_red[i]; S += s_red2[i]; }
            float recon = S * (1.0f / ((float)BATCH * OUT_F));
            float reg   = 0.001f * R * (1.0f / ((float)IN_F * (float)BITS));
            if (out_size > 0) out[0] = recon + reg;
            if (out_size > 1) out[1] = recon;
            if (out_size > 2) out[2] = reg;
            g_ticket = 0;   // reset for next graph replay
        }
    }
}

// ---------------- launch ----------------
extern "C" void kernel_launch(void* const* d_in, const int* in_sizes, int n_in,
                              void* d_out, int out_size) {
    const float* latent   = (const float*)d_in[0];
    const float* true_sum = (const float*)d_in[1];
    const float* weight   = (const float*)d_in[2];

    static int smem_set = 0;
    if (!smem_set) {
        cudaFuncSetAttribute(k_gemm, cudaFuncAttributeMaxDynamicSharedMemorySize,
                             DSMEM_BYTES);
        smem_set = 1;
    }

    k_pre<<<4096, 256>>>(weight, latent);
    k_gemm<<<dim3(GX, GY, KSPLIT), 256, DSMEM_BYTES>>>();
    k_loss<<<NLOSS, 256>>>(true_sum, (float*)d_out, out_size);
}

// round 14
// speedup vs baseline: 1.0900x; 1.0680x over previous
#include <cuda_runtime.h>
#include <cuda_bf16.h>
#include <cstdint>

#define IN_F   4096
#define OUT_F  768
#define BITS   6144
#define BATCH  1024

#define BM 64
#define BN 64
#define BKK 64
#define KSPLIT 2
#define KSLICE (IN_F / KSPLIT)   // 2048
#define NKC (KSLICE / BKK)       // 32
#define NSTAGE 4
#define GX (OUT_F / BN)          // 12
#define GY (BATCH / BM)          // 16
#define A_ST (BM * BKK)          // 4096 u16
#define B_ST (BN * BKK)          // 4096 u16
#define DSMEM_BYTES (NSTAGE * (A_ST + B_ST) * 2)   // 65536
#define NLOSS 768

// ---------------- device scratch ----------------
__device__ __nv_bfloat16 g_wT[(size_t)OUT_F * IN_F];
__device__ __nv_bfloat16 g_lat[(size_t)BATCH * IN_F];
__device__ float g_pred[KSPLIT][(size_t)BATCH * OUT_F];
__device__ float g_reg_part[3072];
__device__ float g_recon_part[NLOSS];
__device__ int   g_ticket;

// ---------------- helpers ----------------
__device__ __forceinline__ float tanh_fast(float x) {
    float y; asm("tanh.approx.f32 %0, %1;" : "=f"(y) : "f"(x)); return y;
}
__device__ __forceinline__ uint32_t cvta_s(const void* p) {
    return (uint32_t)__cvta_generic_to_shared(p);
}
#define CP_ASYNC16(s, g) asm volatile("cp.async.cg.shared.global [%0], [%1], 16;\n" :: "r"(s), "l"(g))
#define CP_COMMIT        asm volatile("cp.async.commit_group;\n" ::: "memory")
#define CP_WAIT0         asm volatile("cp.async.wait_group 0;\n" ::: "memory")
#define CP_WAIT1         asm volatile("cp.async.wait_group 1;\n" ::: "memory")
#define CP_WAIT2         asm volatile("cp.async.wait_group 2;\n" ::: "memory")
#define LDSM4(r0, r1, r2, r3, a) \
    asm volatile("ldmatrix.sync.aligned.m8n8.x4.shared.b16 {%0,%1,%2,%3}, [%4];\n" \
                 : "=r"(r0), "=r"(r1), "=r"(r2), "=r"(r3) : "r"(a))
#define MMA(d, a, b0, b1) \
    asm volatile("mma.sync.aligned.m16n8k16.row.col.f32.bf16.bf16.f32 " \
                 "{%0,%1,%2,%3},{%4,%5,%6,%7},{%8,%9},{%0,%1,%2,%3};\n" \
                 : "+f"(d[0]), "+f"(d[1]), "+f"(d[2]), "+f"(d[3]) \
                 : "r"(a[0]), "r"(a[1]), "r"(a[2]), "r"(a[3]), "r"(b0), "r"(b1))

// ---------------- fused pre-pass (validated) ----------------
__global__ void k_pre(const float* __restrict__ w, const float* __restrict__ lat) {
    int bx = blockIdx.x;
    int t = threadIdx.x;

    if (bx < 3072) {
        __shared__ float s_iw[32][33];
        __shared__ float s_red[8];
        const float pwh[8] = {0.5f, 1.f, 2.f, 4.f, 8.f, 16.f, 32.f, -64.f};

        int k0 = (bx & 127) * 32;
        int n0 = (bx >> 7) * 32;

        float regloc = 0.f;
#pragma unroll
        for (int i = 0; i < 4; i++) {
            int c = t + i * 256;
            int kk = c >> 5, nn = c & 31;
            const float4* p = reinterpret_cast<const float4*>(
                w + (size_t)(k0 + kk) * BITS + (size_t)(n0 + nn) * 8);
            float4 w0 = p[0], w1 = p[1];
            float xs[8] = {w0.x, w0.y, w0.z, w0.w, w1.x, w1.y, w1.z, w1.w};
            float iwt = 0.f, sab = 0.f;
#pragma unroll
            for (int b = 0; b < 8; b++) {
                float th = tanh_fast(0.5f * xs[b]);
                iwt = fmaf(th, pwh[b], iwt);
                sab += fabsf(th);
            }
            s_iw[kk][nn] = iwt - 0.5f;
            regloc += fmaf(-0.5f, sab, 4.0f);
        }
        __syncthreads();
#pragma unroll
        for (int i = 0; i < 4; i++) {
            int c = t + i * 256;
            int nn = c >> 5, kk = c & 31;
            g_wT[(size_t)(n0 + nn) * IN_F + (k0 + kk)] = __float2bfloat16(s_iw[kk][nn]);
        }
#pragma unroll
        for (int o = 16; o > 0; o >>= 1)
            regloc += __shfl_xor_sync(0xffffffffu, regloc, o);
        if ((t & 31) == 0) s_red[t >> 5] = regloc;
        __syncthreads();
        if (t == 0) {
            float s = 0.f;
#pragma unroll
            for (int i = 0; i < 8; i++) s += s_red[i];
            g_reg_part[bx] = s;
        }
    } else {
        int i = (bx - 3072) * 256 + t;
        const int stride = 1024 * 256;
        const float4* src = reinterpret_cast<const float4*>(lat);
        __nv_bfloat162* o = reinterpret_cast<__nv_bfloat162*>(g_lat);
        float4 v[4];
#pragma unroll
        for (int j = 0; j < 4; j++) v[j] = src[i + j * stride];
#pragma unroll
        for (int j = 0; j < 4; j++) {
            int idx = i + j * stride;
            o[2 * idx]     = __floats2bfloat162_rn(v[j].x, v[j].y);
            o[2 * idx + 1] = __floats2bfloat162_rn(v[j].z, v[j].w);
        }
    }
}

// int_sum(r,n)/255 from true_sum
__device__ __forceinline__ float tval(const float* __restrict__ ts, int r, int n) {
    const float4* p = reinterpret_cast<const float4*>(ts + ((size_t)r * OUT_F + n) * 8);
    float4 a = p[0], b = p[1];
    return (a.x + 2.f * a.y + 4.f * a.z + 8.f * a.w
            + 16.f * b.x + 32.f * b.y + 64.f * b.z - 128.f * b.w) * (1.0f / 255.0f);
}

// stage loader (unchanged)
__device__ __forceinline__ void load_tile(
    uint16_t* Asb, uint16_t* Bsb,
    const __nv_bfloat16* gA, const __nv_bfloat16* gB, int kbase, int t)
{
#pragma unroll
    for (int j = 0; j < 2; j++) {
        int id = t + j * 256;
        int row = id >> 3, c = id & 7;
        int sw = (c ^ (row & 7)) << 3;
        CP_ASYNC16(cvta_s(&Asb[row * BKK + sw]),
                   gA + (size_t)row * IN_F + kbase + c * 8);
        CP_ASYNC16(cvta_s(&Bsb[row * BKK + sw]),
                   gB + (size_t)row * IN_F + kbase + c * 8);
    }
}

// split-K GEMM, R14: in-CTA k-split. 8 warps = 2 k-halves x (2m x 2n), warp tile 32x32.
// Per-chunk smem reads 48KB -> 32KB. Final 16KB smem merge of k-half partials.
__global__ void __launch_bounds__(256, 3)
k_gemm() {
    extern __shared__ __align__(16) uint8_t dsm[];
    uint16_t* As = (uint16_t*)dsm;             // NSTAGE * A_ST
    uint16_t* Bs = As + NSTAGE * A_ST;         // NSTAGE * B_ST

    int n0 = blockIdx.x * BN;
    int m0 = blockIdx.y * BM;
    int z  = blockIdx.z;
    int t = threadIdx.x;
    int wid = t >> 5, lane = t & 31;
    int wm = wid & 1, wn = (wid >> 1) & 1, kh = wid >> 2;   // quadrant + k-half

    const __nv_bfloat16* gA = g_lat + (size_t)m0 * IN_F + z * KSLICE;
    const __nv_bfloat16* gB = g_wT + (size_t)n0 * IN_F + z * KSLICE;

    float acc[2][4][4] = {};   // [mt][nt][c], warp tile 32x32

    // ldmatrix lane addressing
    int rAq = wm * 32 + (lane & 15);            // + mt*16
    int kA  = lane >> 4;                        // +0/+1 k8
    int rBq = wn * 32 + ((lane >> 4) << 3) + (lane & 7);   // + j*16
    int kB  = (lane >> 3) & 1;

    // prologue: stages 0..2
    load_tile(As, Bs, gA, gB, 0, t); CP_COMMIT;
    load_tile(As + A_ST, Bs + B_ST, gA, gB, BKK, t); CP_COMMIT;
    load_tile(As + 2 * A_ST, Bs + 2 * B_ST, gA, gB, 2 * BKK, t); CP_COMMIT;

    int buf = 0;
    for (int kc = 0; kc < NKC; kc++) {
        if (kc < NKC - 2)       { CP_WAIT2; }
        else if (kc == NKC - 2) { CP_WAIT1; }
        else                    { CP_WAIT0; }
        __syncthreads();

        if (kc + 3 < NKC) {
            int b3 = buf + 3; if (b3 >= NSTAGE) b3 -= NSTAGE;
            load_tile(As + b3 * A_ST, Bs + b3 * B_ST, gA, gB, (kc + 3) * BKK, t);
            CP_COMMIT;
        }

        const uint16_t* Ab = As + buf * A_ST;
        const uint16_t* Bb = Bs + buf * B_ST;
#pragma unroll
        for (int s = 0; s < 2; s++) {          // 2 k16 steps in this warp's k-half
            int cb = kh * 4 + s * 2;           // k8-chunk base
            uint32_t af[2][4], bf[2][4];
#pragma unroll
            for (int mt = 0; mt < 2; mt++) {
                int r = rAq + mt * 16;
                int c = cb + kA;
                LDSM4(af[mt][0], af[mt][1], af[mt][2], af[mt][3],
                      cvta_s(&Ab[r * BKK + ((c ^ (r & 7)) << 3)]));
            }
#pragma unroll
            for (int j = 0; j < 2; j++) {
                int r = rBq + j * 16;
                int c = cb + kB;
                LDSM4(bf[j][0], bf[j][1], bf[j][2], bf[j][3],
                      cvta_s(&Bb[r * BKK + ((c ^ (r & 7)) << 3)]));
            }
#pragma unroll
            for (int mt = 0; mt < 2; mt++)
#pragma unroll
                for (int j = 0; j < 2; j++) {
                    MMA(acc[mt][2 * j],     af[mt], bf[j][0], bf[j][1]);
                    MMA(acc[mt][2 * j + 1], af[mt], bf[j][2], bf[j][3]);
                }
        }
        buf++; if (buf >= NSTAGE) buf = 0;
    }

    // merge k-halves: kh=1 warps stash acc in smem, kh=0 warps add
    __syncthreads();                            // all LDSM reads done; reuse As region
    float* M = reinterpret_cast<float*>(dsm);   // 4 quadrants x 4KB = 16KB
    float* afl = &acc[0][0][0];                 // 32 floats
    int quad = wm * 2 + wn;
    if (kh == 1) {
#pragma unroll
        for (int r = 0; r < 32; r++)
            M[quad * 1024 + r * 32 + lane] = afl[r];
    }
    __syncthreads();

    if (kh == 0) {
#pragma unroll
        for (int r = 0; r < 32; r++)
            afl[r] += M[quad * 1024 + r * 32 + lane];

        // store fp32 partials for this z-slice (warps 0-3 cover full 64x64)
        float* P = g_pred[z];
        int gid = lane >> 2, tig = lane & 3;
#pragma unroll
        for (int mt = 0; mt < 2; mt++)
#pragma unroll
            for (int nt = 0; nt < 4; nt++) {
                int r  = m0 + wm * 32 + mt * 16 + gid;
                int nc = n0 + wn * 32 + nt * 8 + tig * 2;
                *reinterpret_cast<float2*>(&P[(size_t)r * OUT_F + nc]) =
                    make_float2(acc[mt][nt][0], acc[mt][nt][1]);
                *reinterpret_cast<float2*>(&P[(size_t)(r + 8) * OUT_F + nc]) =
                    make_float2(acc[mt][nt][2], acc[mt][nt][3]);
            }
    }
}

// loss: pred = p0+p1, (pred/255 - int_sum/255)^2; last-block final reduction
__global__ void k_loss(const float* __restrict__ ts,
                       float* __restrict__ out, int out_size) {
    __shared__ float s_red[8], s_red2[8];
    __shared__ int s_last;
    int t = threadIdx.x, bid = blockIdx.x;
    int base = (bid * 256 + t) * 4;
    int r = base / OUT_F, n = base % OUT_F;

    float4 p0 = *reinterpret_cast<const float4*>(&g_pred[0][base]);
    float4 p1 = *reinterpret_cast<const float4*>(&g_pred[1][base]);
    float e0 = fmaf(p0.x + p1.x, 1.f / 255.f, -tval(ts, r, n));
    float e1 = fmaf(p0.y + p1.y, 1.f / 255.f, -tval(ts, r, n + 1));
    float e2 = fmaf(p0.z + p1.z, 1.f / 255.f, -tval(ts, r, n + 2));
    float e3 = fmaf(p0.w + p1.w, 1.f / 255.f, -tval(ts, r, n + 3));
    float lsum = e0 * e0 + e1 * e1 + e2 * e2 + e3 * e3;

#pragma unroll
    for (int o = 16; o > 0; o >>= 1)
        lsum += __shfl_xor_sync(0xffffffffu, lsum, o);
    if ((t & 31) == 0) s_red[t >> 5] = lsum;
    __syncthreads();

    if (t == 0) {
        float s = 0.f;
#pragma unroll
        for (int i = 0; i < 8; i++) s += s_red[i];
        g_recon_part[bid] = s;
        __threadfence();
        int old = atomicAdd(&g_ticket, 1);
        s_last = (old == NLOSS - 1) ? 1 : 0;
    }
    __syncthreads();

    if (s_last) {
        float rr = 0.f, ss = 0.f;
        for (int i = t; i < 3072; i += 256) rr += __ldcg(&g_reg_part[i]);
        for (int i = t; i < NLOSS; i += 256) ss += __ldcg(&g_recon_part[i]);
#pragma unroll
        for (int o = 16; o > 0; o >>= 1) {
            rr += __shfl_xor_sync(0xffffffffu, rr, o);
            ss += __shfl_xor_sync(0xffffffffu, ss, o);
        }
        if ((t & 31) == 0) { s_red[t >> 5] = rr; s_red2[t >> 5] = ss; }
        __syncthreads();
        if (t == 0) {
            float R = 0.f, S = 0.f;
#pragma unroll
            for (int i = 0; i < 8; i++) { R += s_red[i]; S += s_red2[i]; }
            float recon = S * (1.0f / ((float)BATCH * OUT_F));
            float reg   = 0.001f * R * (1.0f / ((float)IN_F * (float)BITS));
            if (out_size > 0) out[0] = recon + reg;
            if (out_size > 1) out[1] = recon;
            if (out_size > 2) out[2] = reg;
            g_ticket = 0;
        }
    }
}

// ---------------- launch ----------------
extern "C" void kernel_launch(void* const* d_in, const int* in_sizes, int n_in,
                              void* d_out, int out_size) {
    const float* latent   = (const float*)d_in[0];
    const float* true_sum = (const float*)d_in[1];
    const float* weight   = (const float*)d_in[2];

    static int smem_set = 0;
    if (!smem_set) {
        cudaFuncSetAttribute(k_gemm, cudaFuncAttributeMaxDynamicSharedMemorySize,
                             DSMEM_BYTES);
        smem_set = 1;
    }

    k_pre<<<4096, 256>>>(weight, latent);
    k_gemm<<<dim3(GX, GY, KSPLIT), 256, DSMEM_BYTES>>>();
    k_loss<<<NLOSS, 256>>>(true_sum, (float*)d_out, out_size);
}